// round 9
// baseline (speedup 1.0000x reference)
#include <cuda_runtime.h>

#define NB   4
#define NN   2048
#define NT   8192
#define HH   64
#define G3   192
#define KK   8
#define OUTD 32
#define CCH  128
#define CL   64
#define CW   256

typedef unsigned long long ull;

__device__ __forceinline__ ull ffma2(ull a, ull b, ull c) {
    ull d; asm("fma.rn.f32x2 %0, %1, %2, %3;" : "=l"(d) : "l"(a), "l"(b), "l"(c)); return d;
}
__device__ __forceinline__ float2 upk(ull a) {
    float2 r; asm("mov.b64 {%0,%1}, %2;" : "=f"(r.x), "=f"(r.y) : "l"(a)); return r;
}

// ---------------- device scratch (no allocations) ----------------
__device__ float g_xp[2][NT][G3];
__device__ float g_h[2][NT][HH];
__device__ float g_vals[NT][KK];
__device__ int   g_idx[NT][KK];
__device__ float g_deg[NT];
__device__ float g_dinv[NT];
__device__ float g_xw[NT][HH];
__device__ float g_o1[NT][HH];
__device__ float g_o2[NT][HH];
__device__ float g_sum[HH];
__device__ float g_sqs[HH];
__device__ float g_Wps[OUTD * HH];
__device__ float g_bps[OUTD];

// ---------------- zero / init ----------------
__global__ void k_zero() {
    int i = blockIdx.x * blockDim.x + threadIdx.x;
    int stride = gridDim.x * blockDim.x;
    float* o1 = &g_o1[0][0];
    float* o2 = &g_o2[0][0];
    for (int e = i; e < NT * HH; e += stride) { o1[e] = 0.f; o2[e] = 0.f; }
    if (i < NT) g_deg[i] = 1.0f;          // self-loop weight
    if (i < HH) { g_sum[i] = 0.f; g_sqs[i] = 0.f; }
}

// ---------------- xp = seq @ Wih.T + bih (both GRUs) ----------------
__global__ __launch_bounds__(192) void k_xp(const float* __restrict__ x_seq,
                                            const float* __restrict__ W0, const float* __restrict__ bi0,
                                            const float* __restrict__ W1, const float* __restrict__ bi1)
{
    int gi = blockIdx.y;
    const float* W  = gi ? W1  : W0;
    const float* bi = gi ? bi1 : bi0;
    int t0 = blockIdx.x * 32;
    int b  = t0 >> 11;
    int n0 = t0 & 2047;
    __shared__ __align__(16) float sT[64 * 32];   // sT[f*32+tt]
    int tid = threadIdx.x;
    for (int e = tid; e < 2048; e += 192) {
        int f = e >> 5, tt = e & 31;
        sT[e] = x_seq[((b * 8 + 7) * 64 + f) * 2048 + n0 + tt];
    }
    float w[64];
    const float4* wr = (const float4*)(W + tid * 64);
#pragma unroll
    for (int q = 0; q < 16; q++) { float4 v = wr[q]; w[4*q]=v.x; w[4*q+1]=v.y; w[4*q+2]=v.z; w[4*q+3]=v.w; }
    float bb = bi[tid];
    __syncthreads();
#pragma unroll 1
    for (int tg = 0; tg < 8; tg++) {
        float a0 = bb, a1 = bb, a2 = bb, a3 = bb;
#pragma unroll
        for (int k = 0; k < 64; k++) {
            float4 sv = *(const float4*)&sT[k * 32 + tg * 4];
            a0 += w[k] * sv.x; a1 += w[k] * sv.y; a2 += w[k] * sv.z; a3 += w[k] * sv.w;
        }
        int tt = tg * 4;
        g_xp[gi][t0 + tt    ][tid] = a0;
        g_xp[gi][t0 + tt + 1][tid] = a1;
        g_xp[gi][t0 + tt + 2][tid] = a2;
        g_xp[gi][t0 + tt + 3][tid] = a3;
    }
}

// ---------------- chunked GRU scan (contraction / warmup trick) ----------------
__global__ __launch_bounds__(192, 1) void k_gru(const float* __restrict__ Whh0, const float* __restrict__ bhh0,
                                                const float* __restrict__ Whh1, const float* __restrict__ bhh1)
{
    int gi = blockIdx.y;
    const float* Whh = gi ? Whh1 : Whh0;
    const float* bhh = gi ? bhh1 : bhh0;
    int c = blockIdx.x;
    int tstart = c * CL - CW; if (tstart < 0) tstart = 0;
    int twrite = c * CL;
    int tend   = c * CL + CL;
    int tid = threadIdx.x;

    ull w2[32];
    const ull* wr = (const ull*)(Whh + tid * HH);
#pragma unroll
    for (int q = 0; q < 32; q++) w2[q] = wr[q];
    float bb = bhh[tid];

    __shared__ __align__(16) float shh[HH];
    __shared__ float shs[G3];
    __shared__ float sxp[G3];
    if (tid < HH) shh[tid] = 0.f;
    __syncthreads();

    const float* xp = &g_xp[gi][0][0];
    float xc = xp[tstart * G3 + tid];

#pragma unroll 1
    for (int t = tstart; t < tend; t++) {
        int tn = (t + 1 < tend) ? (t + 1) : t;       // clamp prefetch inside chunk
        float xn = xp[tn * G3 + tid];

        const ull* hv = (const ull*)shh;
        ull a0 = 0ull, a1 = 0ull;
#pragma unroll
        for (int q = 0; q < 32; q += 2) {
            a0 = ffma2(w2[q],     hv[q],     a0);
            a1 = ffma2(w2[q + 1], hv[q + 1], a1);
        }
        float2 p0 = upk(a0), p1 = upk(a1);
        float hp = (p0.x + p0.y) + (p1.x + p1.y) + bb;
        shs[tid] = hp;
        sxp[tid] = xc;
        __syncthreads();
        if (tid < HH) {
            float r  = __fdividef(1.f, 1.f + __expf(-(sxp[tid]       + shs[tid])));
            float z  = __fdividef(1.f, 1.f + __expf(-(sxp[tid + 64]  + shs[tid + 64])));
            float a  = sxp[tid + 128] + r * shs[tid + 128];
            float ng = 1.f - __fdividef(2.f, __expf(2.f * a) + 1.f);   // tanh
            float hn = (1.f - z) * ng + z * shh[tid];
            shh[tid] = hn;
            if (t >= twrite) g_h[gi][t][tid] = hn;
        }
        __syncthreads();
        xc = xn;
    }
}

// ---------------- fused similarity + top-8 (no g_sim round trip) ----------------
__global__ __launch_bounds__(256, 1) void k_simtop() {
    __shared__ __align__(16) float sA[64 * 66];
    __shared__ __align__(16) float sB[256 * 66];     // reused as out-tile [64][257]
    __shared__ float s_tv[64 * 8];
    __shared__ int   s_ti[64 * 8];
    int b = blockIdx.y, r0 = blockIdx.x * 64;
    int tid = threadIdx.x, w = tid >> 5, mp = tid & 31;

    for (int e = tid; e < 64 * 32; e += 256) {
        int r = e >> 5, c2 = e & 31;
        *(float2*)&sA[r * 66 + c2 * 2] = *(const float2*)&g_h[0][b * NN + r0 + r][c2 * 2];
    }
    for (int e = tid; e < 512; e += 256) { s_tv[e] = -3e38f; s_ti[e] = 0; }

    ull acc[8][8];
#pragma unroll
    for (int r = 0; r < 8; r++)
#pragma unroll
        for (int j = 0; j < 8; j++) acc[r][j] = 0ull;

    int base = b * NN;
#pragma unroll 1
    for (int tile = 0; tile < 8; tile++) {
        __syncthreads();
        for (int e = tid; e < 256 * 32; e += 256) {
            int r = e >> 5, c2 = e & 31;
            *(float2*)&sB[r * 66 + c2 * 2] = *(const float2*)&g_h[0][base + tile * 256 + r][c2 * 2];
        }
        __syncthreads();
#pragma unroll 4
        for (int kc = 0; kc < 32; kc++) {
            ull bv[8];
#pragma unroll
            for (int j = 0; j < 8; j++) bv[j] = *(const ull*)&sB[(mp + 32 * j) * 66 + 2 * kc];
#pragma unroll
            for (int r = 0; r < 8; r++) {
                ull av = *(const ull*)&sA[(w * 8 + r) * 66 + 2 * kc];
#pragma unroll
                for (int j = 0; j < 8; j++) acc[r][j] = ffma2(av, bv[j], acc[r][j]);
            }
        }
        __syncthreads();   // all warps done reading sB -> safe to overwrite as out-tile
#pragma unroll
        for (int r = 0; r < 8; r++) {
            int lw = w * 8 + r;
            int row = r0 + lw;
#pragma unroll
            for (int j = 0; j < 8; j++) {
                int m = tile * 256 + mp + 32 * j;
                float2 p = upk(acc[r][j]);
                float v = p.x + p.y;
                if (m == row) v = -1e9f;
                sB[lw * 257 + mp + 32 * j] = v;
                acc[r][j] = 0ull;
            }
        }
        __syncthreads();
        // per-warp top-8 merge: warp w owns rows w*8 .. w*8+7
#pragma unroll 1
        for (int r = 0; r < 8; r++) {
            int lw = w * 8 + r;
            float vv[KK]; int ii[KK];
#pragma unroll
            for (int q = 0; q < KK; q++) { vv[q] = -3e38f; ii[q] = 0; }
#pragma unroll
            for (int s = 0; s < 8; s++) {
                int m = mp + 32 * s;
                float v = sB[lw * 257 + m];
                int gidx = tile * 256 + m;
                if (v > vv[7]) {
                    vv[7] = v; ii[7] = gidx;
#pragma unroll
                    for (int s2 = 7; s2 > 0; s2--) {
                        if (vv[s2] > vv[s2 - 1]) {
                            float tv = vv[s2]; vv[s2] = vv[s2 - 1]; vv[s2 - 1] = tv;
                            int   ti = ii[s2]; ii[s2] = ii[s2 - 1]; ii[s2 - 1] = ti;
                        }
                    }
                }
            }
            // lanes 0..7 inject the running top-8 as extra candidates
            if (mp < 8) {
                float v = s_tv[lw * 8 + mp];
                int gidx = s_ti[lw * 8 + mp];
                if (v > vv[7]) {
                    vv[7] = v; ii[7] = gidx;
#pragma unroll
                    for (int s2 = 7; s2 > 0; s2--) {
                        if (vv[s2] > vv[s2 - 1]) {
                            float tv = vv[s2]; vv[s2] = vv[s2 - 1]; vv[s2 - 1] = tv;
                            int   ti = ii[s2]; ii[s2] = ii[s2 - 1]; ii[s2 - 1] = ti;
                        }
                    }
                }
            }
            int head = 0;
#pragma unroll
            for (int q = 0; q < KK; q++) {
                float myv = (head < KK) ? vv[head] : -3e38f;
                int   myi = (head < KK) ? ii[head] : 0;
                float bestv = myv; int besti = myi; int bestl = mp;
#pragma unroll
                for (int off = 16; off > 0; off >>= 1) {
                    float ov = __shfl_xor_sync(0xffffffffu, bestv, off);
                    int   oi = __shfl_xor_sync(0xffffffffu, besti, off);
                    int   ol = __shfl_xor_sync(0xffffffffu, bestl, off);
                    if (ov > bestv || (ov == bestv && ol < bestl)) { bestv = ov; besti = oi; bestl = ol; }
                }
                if (mp == bestl) head++;
                if (mp == 0) { s_tv[lw * 8 + q] = bestv; s_ti[lw * 8 + q] = besti; }
            }
            __syncwarp();
        }
    }
    __syncthreads();
    for (int e = tid; e < 512; e += 256) {
        int row = r0 + (e >> 3), q = e & 7;
        int t = base + row;
        float v = s_tv[e];
        int col = base + s_ti[e];
        g_vals[t][q] = v;
        g_idx[t][q]  = col;
        atomicAdd(&g_deg[col], v);
    }
}

// ---------------- dinv = deg^{-1/2}, inf -> 0 ----------------
__global__ void k_dinv() {
    int t = blockIdx.x * blockDim.x + threadIdx.x;
    if (t < NT) {
        float r = rsqrtf(g_deg[t]);
        if (isinf(r)) r = 0.f;
        g_dinv[t] = r;
    }
}

// ---------------- xw = src @ W.T ----------------
__global__ __launch_bounds__(256) void k_xw(int layer, const float* __restrict__ W) {
    int t0 = blockIdx.x * 16;
    __shared__ float sW[64][65];
    __shared__ float sx[16][64];
    int tid = threadIdx.x;
    const float* src = layer ? &g_o1[0][0] : &g_h[1][0][0];
    for (int e = tid; e < 4096; e += 256) sW[e >> 6][e & 63] = W[e];
    for (int e = tid; e < 1024; e += 256) sx[e >> 6][e & 63] = src[(t0 + (e >> 6)) * 64 + (e & 63)];
    __syncthreads();
    int h = tid & 63, tq = tid >> 6;
    float acc[4] = {0.f, 0.f, 0.f, 0.f};
#pragma unroll 1
    for (int k = 0; k < 64; k++) {
        float wv = sW[h][k];
#pragma unroll
        for (int r = 0; r < 4; r++) acc[r] += wv * sx[tq * 4 + r][k];
    }
    float* xw = &g_xw[0][0];
#pragma unroll
    for (int r = 0; r < 4; r++) xw[(t0 + tq * 4 + r) * 64 + h] = acc[r];
}

// ---------------- edge scatter (atomics), 32 edges per block, 65536 total ----------------
__global__ __launch_bounds__(256) void k_scatter(int layer) {
    int h = threadIdx.x & 63;
    int sub = threadIdx.x >> 6;
    int e0 = blockIdx.x * 32;
    float* dst = layer ? &g_o2[0][0] : &g_o1[0][0];
#pragma unroll
    for (int q = 0; q < 8; q++) {
        int e = e0 + q * 4 + sub;
        int n = e >> 3, k = e & 7;
        int col  = g_idx[n][k];
        float w  = g_vals[n][k];
        float nr = g_dinv[n] * w * g_dinv[col];
        atomicAdd(&dst[col * 64 + h], nr * g_xw[n][h]);
    }
}

// ---------------- self-loop + bias + relu (layer 0) ----------------
__global__ void k_finish(const float* __restrict__ bias) {
    int i = blockIdx.x * blockDim.x + threadIdx.x;
    if (i >= NT * HH) return;
    int t = i >> 6, h = i & 63;
    float d = g_dinv[t];
    float v = g_o1[0][i >> 6 ? 0 : 0];  // placeholder avoided below
    float* buf = &g_o1[0][0];
    v = buf[i] + d * d * (&g_xw[0][0])[i] + bias[h];
    buf[i] = v > 0.f ? v : 0.f;
}

// ---------------- layer-1 finish + BN stats fused ----------------
__global__ __launch_bounds__(256) void k_finish_stats(const float* __restrict__ bias) {
    int h = threadIdx.x & 63, part = threadIdx.x >> 6;
    int rbase = blockIdx.x * 64;
    float* o2 = &g_o2[0][0];
    const float* xw = &g_xw[0][0];
    float bb = bias[h];
    float s = 0.f, s2 = 0.f;
#pragma unroll 4
    for (int sI = 0; sI < 16; sI++) {
        int t = rbase + part + 4 * sI;
        float d = g_dinv[t];
        int i = t * 64 + h;
        float v = o2[i] + d * d * xw[i] + bb;
        v = v > 0.f ? v : 0.f;
        o2[i] = v;
        s += v; s2 += v * v;
    }
    __shared__ float ss[4][64], sq[4][64];
    ss[part][h] = s; sq[part][h] = s2;
    __syncthreads();
    if (threadIdx.x < 64) {
        atomicAdd(&g_sum[h], ss[0][h] + ss[1][h] + ss[2][h] + ss[3][h]);
        atomicAdd(&g_sqs[h], sq[0][h] + sq[1][h] + sq[2][h] + sq[3][h]);
    }
}

// ---------------- fold BN into predictor ----------------
__global__ void k_prep(const float* __restrict__ gamma, const float* __restrict__ beta,
                       const float* __restrict__ Wp, const float* __restrict__ bp) {
    __shared__ float ssc[64], ssh[64];
    int tid = threadIdx.x;
    if (tid < 64) {
        float mu  = g_sum[tid] * (1.f / 8192.f);
        float var = g_sqs[tid] * (1.f / 8192.f) - mu * mu;
        float sc  = gamma[tid] * rsqrtf(var + 1e-5f);
        ssc[tid] = sc;
        ssh[tid] = beta[tid] - mu * sc;
    }
    __syncthreads();
    for (int e = tid; e < OUTD * HH; e += 256) g_Wps[e] = Wp[e] * ssc[e & 63];
    if (tid < OUTD) {
        float a = bp[tid];
        for (int h = 0; h < 64; h++) a += ssh[h] * Wp[tid * 64 + h];
        g_bps[tid] = a;
    }
}

// ---------------- final projection ----------------
__global__ __launch_bounds__(256) void k_out(float* __restrict__ out) {
    int t0 = blockIdx.x * 8;
    __shared__ float sr[8][64];
    int tid = threadIdx.x;
    const float* o2 = &g_o2[0][0];
    for (int e = tid; e < 512; e += 256) sr[e >> 6][e & 63] = o2[(t0 + (e >> 6)) * 64 + (e & 63)];
    __syncthreads();
    int tl = tid >> 5, o = tid & 31;
    float acc = g_bps[o];
#pragma unroll 1
    for (int h = 0; h < 64; h++) acc += sr[tl][h] * g_Wps[o * 64 + h];
    out[(t0 + tl) * 32 + o] = acc;
}

extern "C" void kernel_launch(void* const* d_in, const int* in_sizes, int n_in,
                              void* d_out, int out_size) {
    const float* x_seq = (const float*)d_in[0];
    const float* Wih_s = (const float*)d_in[1];
    const float* Whh_s = (const float*)d_in[2];
    const float* bih_s = (const float*)d_in[3];
    const float* bhh_s = (const float*)d_in[4];
    const float* Wih   = (const float*)d_in[5];
    const float* Whh   = (const float*)d_in[6];
    const float* bih   = (const float*)d_in[7];
    const float* bhh   = (const float*)d_in[8];
    const float* W1    = (const float*)d_in[9];
    const float* b1    = (const float*)d_in[10];
    const float* W2    = (const float*)d_in[11];
    const float* b2    = (const float*)d_in[12];
    const float* gamma = (const float*)d_in[13];
    const float* beta  = (const float*)d_in[14];
    const float* Wp    = (const float*)d_in[15];
    const float* bp    = (const float*)d_in[16];
    float* out = (float*)d_out;

    k_zero<<<512, 256>>>();
    k_xp<<<dim3(256, 2), 192>>>(x_seq, Wih_s, bih_s, Wih, bih);
    k_gru<<<dim3(CCH, 2), 192>>>(Whh_s, bhh_s, Whh, bhh);
    k_simtop<<<dim3(32, 4), 256>>>();
    k_dinv<<<32, 256>>>();
    k_xw<<<512, 256>>>(0, W1);
    k_scatter<<<2048, 256>>>(0);
    k_finish<<<2048, 256>>>(b1);
    k_xw<<<512, 256>>>(1, W2);
    k_scatter<<<2048, 256>>>(1);
    k_finish_stats<<<128, 256>>>(b2);
    k_prep<<<1, 256>>>(gamma, beta, Wp, bp);
    k_out<<<1024, 256>>>(out);
}

// round 10
// speedup vs baseline: 1.3514x; 1.3514x over previous
#include <cuda_runtime.h>

#define NB   4
#define NN   2048
#define NT   8192
#define HH   64
#define G3   192
#define KK   8
#define OUTD 32
#define CCH  64
#define CL   128
#define CW   192

typedef unsigned long long ull;

__device__ __forceinline__ ull ffma2(ull a, ull b, ull c) {
    ull d; asm("fma.rn.f32x2 %0, %1, %2, %3;" : "=l"(d) : "l"(a), "l"(b), "l"(c)); return d;
}
__device__ __forceinline__ float2 upk(ull a) {
    float2 r; asm("mov.b64 {%0,%1}, %2;" : "=f"(r.x), "=f"(r.y) : "l"(a)); return r;
}

// ---------------- device scratch (no allocations) ----------------
__device__ float g_xp[2][NT][G3];
__device__ float g_h[2][NT][HH];
__device__ float g_sim[NB * NN * NN];
__device__ float g_vals[NT][KK];
__device__ int   g_idx[NT][KK];
__device__ float g_deg[NT];
__device__ float g_dinv[NT];
__device__ float g_xw[NT][HH];
__device__ float g_o1[NT][HH];
__device__ float g_o2[NT][HH];
__device__ float g_sum[HH];
__device__ float g_sqs[HH];
__device__ float g_Wps[OUTD * HH];
__device__ float g_bps[OUTD];

// ---------------- zero / init ----------------
__global__ void k_zero() {
    int i = blockIdx.x * blockDim.x + threadIdx.x;
    int stride = gridDim.x * blockDim.x;
    float* o1 = &g_o1[0][0];
    float* o2 = &g_o2[0][0];
    for (int e = i; e < NT * HH; e += stride) { o1[e] = 0.f; o2[e] = 0.f; }
    if (i < NT) g_deg[i] = 1.0f;          // self-loop weight
    if (i < HH) { g_sum[i] = 0.f; g_sqs[i] = 0.f; }
}

// ---------------- xp = seq @ Wih.T + bih (both GRUs) ----------------
__global__ __launch_bounds__(192) void k_xp(const float* __restrict__ x_seq,
                                            const float* __restrict__ W0, const float* __restrict__ bi0,
                                            const float* __restrict__ W1, const float* __restrict__ bi1)
{
    int gi = blockIdx.y;
    const float* W  = gi ? W1  : W0;
    const float* bi = gi ? bi1 : bi0;
    int t0 = blockIdx.x * 32;
    int b  = t0 >> 11;
    int n0 = t0 & 2047;
    __shared__ __align__(16) float sT[64 * 32];   // sT[f*32+tt]
    int tid = threadIdx.x;
    for (int e = tid; e < 2048; e += 192) {
        int f = e >> 5, tt = e & 31;
        sT[e] = x_seq[((b * 8 + 7) * 64 + f) * 2048 + n0 + tt];
    }
    float w[64];
    const float4* wr = (const float4*)(W + tid * 64);
#pragma unroll
    for (int q = 0; q < 16; q++) { float4 v = wr[q]; w[4*q]=v.x; w[4*q+1]=v.y; w[4*q+2]=v.z; w[4*q+3]=v.w; }
    float bb = bi[tid];
    __syncthreads();
#pragma unroll 1
    for (int tg = 0; tg < 8; tg++) {
        float a0 = bb, a1 = bb, a2 = bb, a3 = bb;
#pragma unroll
        for (int k = 0; k < 64; k++) {
            float4 sv = *(const float4*)&sT[k * 32 + tg * 4];
            a0 += w[k] * sv.x; a1 += w[k] * sv.y; a2 += w[k] * sv.z; a3 += w[k] * sv.w;
        }
        int tt = tg * 4;
        g_xp[gi][t0 + tt    ][tid] = a0;
        g_xp[gi][t0 + tt + 1][tid] = a1;
        g_xp[gi][t0 + tt + 2][tid] = a2;
        g_xp[gi][t0 + tt + 3][tid] = a3;
    }
}

// ---------------- chunked GRU scan (contraction / warmup trick) ----------------
__global__ __launch_bounds__(192, 1) void k_gru(const float* __restrict__ Whh0, const float* __restrict__ bhh0,
                                                const float* __restrict__ Whh1, const float* __restrict__ bhh1)
{
    int gi = blockIdx.y;
    const float* Whh = gi ? Whh1 : Whh0;
    const float* bhh = gi ? bhh1 : bhh0;
    int c = blockIdx.x;
    int tstart = c * CL - CW; if (tstart < 0) tstart = 0;
    int twrite = c * CL;
    int tend   = c * CL + CL;
    int tid = threadIdx.x;

    ull w2[32];
    const ull* wr = (const ull*)(Whh + tid * HH);
#pragma unroll
    for (int q = 0; q < 32; q++) w2[q] = wr[q];
    float bb = bhh[tid];

    __shared__ __align__(16) float shh[HH];
    __shared__ float shs[G3];
    __shared__ float sxp[G3];
    if (tid < HH) shh[tid] = 0.f;
    __syncthreads();

    const float* xp = &g_xp[gi][0][0];
    float xc = xp[tstart * G3 + tid];

#pragma unroll 1
    for (int t = tstart; t < tend; t++) {
        int tn = (t + 1 < tend) ? (t + 1) : t;       // clamp prefetch inside chunk
        float xn = xp[tn * G3 + tid];

        const ull* hv = (const ull*)shh;
        ull a0 = 0ull, a1 = 0ull;
#pragma unroll
        for (int q = 0; q < 32; q += 2) {
            a0 = ffma2(w2[q],     hv[q],     a0);
            a1 = ffma2(w2[q + 1], hv[q + 1], a1);
        }
        float2 p0 = upk(a0), p1 = upk(a1);
        float hp = (p0.x + p0.y) + (p1.x + p1.y) + bb;
        shs[tid] = hp;
        sxp[tid] = xc;
        __syncthreads();
        if (tid < HH) {
            float r  = __fdividef(1.f, 1.f + __expf(-(sxp[tid]       + shs[tid])));
            float z  = __fdividef(1.f, 1.f + __expf(-(sxp[tid + 64]  + shs[tid + 64])));
            float a  = sxp[tid + 128] + r * shs[tid + 128];
            float ng = 1.f - __fdividef(2.f, __expf(2.f * a) + 1.f);   // tanh
            float hn = (1.f - z) * ng + z * shh[tid];
            shh[tid] = hn;
            if (t >= twrite) g_h[gi][t][tid] = hn;
        }
        __syncthreads();
        xc = xn;
    }
}

// ---------------- similarity: 64-row blocks, 512 threads, f32x2 FMA ----------------
__global__ __launch_bounds__(512, 1) void k_sim() {
    __shared__ __align__(16) float sA[64 * 66];
    __shared__ __align__(16) float sB[256 * 66];
    int b = blockIdx.y, r0 = blockIdx.x * 64;
    int tid = threadIdx.x, w = tid >> 5, mp = tid & 31;
    int rg = w >> 1, half = w & 1;     // rowgroup 0..7, column half 0..1

    for (int e = tid; e < 64 * 32; e += 512) {
        int r = e >> 5, c2 = e & 31;
        *(float2*)&sA[r * 66 + c2 * 2] = *(const float2*)&g_h[0][b * NN + r0 + r][c2 * 2];
    }

    ull acc[8][4];
#pragma unroll
    for (int r = 0; r < 8; r++)
#pragma unroll
        for (int j = 0; j < 4; j++) acc[r][j] = 0ull;

    int base = b * NN;
#pragma unroll 1
    for (int tile = 0; tile < 8; tile++) {
        __syncthreads();
        for (int e = tid; e < 256 * 32; e += 512) {
            int r = e >> 5, c2 = e & 31;
            *(float2*)&sB[r * 66 + c2 * 2] = *(const float2*)&g_h[0][base + tile * 256 + r][c2 * 2];
        }
        __syncthreads();
#pragma unroll 4
        for (int kc = 0; kc < 32; kc++) {
            ull bv[4];
#pragma unroll
            for (int j = 0; j < 4; j++) bv[j] = *(const ull*)&sB[(mp + 32 * j + 128 * half) * 66 + 2 * kc];
#pragma unroll
            for (int r = 0; r < 8; r++) {
                ull av = *(const ull*)&sA[(rg * 8 + r) * 66 + 2 * kc];
#pragma unroll
                for (int j = 0; j < 4; j++) acc[r][j] = ffma2(av, bv[j], acc[r][j]);
            }
        }
#pragma unroll
        for (int r = 0; r < 8; r++) {
            int row = r0 + rg * 8 + r;
#pragma unroll
            for (int j = 0; j < 4; j++) {
                int m = tile * 256 + mp + 32 * j + 128 * half;
                float2 p = upk(acc[r][j]);
                float v = p.x + p.y;
                if (m == row) v = -1e9f;
                g_sim[(base + row) * NN + m] = v;
                acc[r][j] = 0ull;
            }
        }
    }
}

// ---------------- top-8 per row (warp shuffle merge) + degree accumulation ----------------
__global__ __launch_bounds__(256) void k_topk() {
    int warp = threadIdx.x >> 5, lane = threadIdx.x & 31;
    int t = blockIdx.x * 8 + warp;
    int b = t >> 11;
    const float* row = &g_sim[t * NN];
    float vv[KK]; int ii[KK];
#pragma unroll
    for (int q = 0; q < KK; q++) { vv[q] = -3e38f; ii[q] = 0; }
#pragma unroll 1
    for (int j = 0; j < 64; j++) {
        int m = j * 32 + lane;
        float v = row[m];
        if (v > vv[7]) {
            vv[7] = v; ii[7] = m;
#pragma unroll
            for (int s = 7; s > 0; s--) {
                if (vv[s] > vv[s - 1]) {
                    float tv = vv[s]; vv[s] = vv[s - 1]; vv[s - 1] = tv;
                    int   ti = ii[s]; ii[s] = ii[s - 1]; ii[s - 1] = ti;
                }
            }
        }
    }
    int head = 0;
#pragma unroll
    for (int q = 0; q < KK; q++) {
        float myv = (head < KK) ? vv[head] : -3e38f;
        int   myi = (head < KK) ? ii[head] : 0;
        float bestv = myv; int besti = myi; int bestl = lane;
#pragma unroll
        for (int off = 16; off > 0; off >>= 1) {
            float ov = __shfl_xor_sync(0xffffffffu, bestv, off);
            int   oi = __shfl_xor_sync(0xffffffffu, besti, off);
            int   ol = __shfl_xor_sync(0xffffffffu, bestl, off);
            if (ov > bestv || (ov == bestv && ol < bestl)) { bestv = ov; besti = oi; bestl = ol; }
        }
        if (lane == bestl) head++;
        if (lane == 0) {
            g_vals[t][q] = bestv;
            int col = b * NN + besti;
            g_idx[t][q] = col;
            atomicAdd(&g_deg[col], bestv);
        }
    }
}

// ---------------- dinv = deg^{-1/2}, inf -> 0 ----------------
__global__ void k_dinv() {
    int t = blockIdx.x * blockDim.x + threadIdx.x;
    if (t < NT) {
        float r = rsqrtf(g_deg[t]);
        if (isinf(r)) r = 0.f;
        g_dinv[t] = r;
    }
}

// ---------------- xw = src @ W.T ----------------
__global__ __launch_bounds__(256) void k_xw(int layer, const float* __restrict__ W) {
    int t0 = blockIdx.x * 16;
    __shared__ float sW[64][65];
    __shared__ float sx[16][64];
    int tid = threadIdx.x;
    const float* src = layer ? &g_o1[0][0] : &g_h[1][0][0];
    for (int e = tid; e < 4096; e += 256) sW[e >> 6][e & 63] = W[e];
    for (int e = tid; e < 1024; e += 256) sx[e >> 6][e & 63] = src[(t0 + (e >> 6)) * 64 + (e & 63)];
    __syncthreads();
    int h = tid & 63, tq = tid >> 6;
    float acc[4] = {0.f, 0.f, 0.f, 0.f};
#pragma unroll 1
    for (int k = 0; k < 64; k++) {
        float wv = sW[h][k];
#pragma unroll
        for (int r = 0; r < 4; r++) acc[r] += wv * sx[tq * 4 + r][k];
    }
    float* xw = &g_xw[0][0];
#pragma unroll
    for (int r = 0; r < 4; r++) xw[(t0 + tq * 4 + r) * 64 + h] = acc[r];
}

// ---------------- edge scatter (atomics), 32 edges per block, 65536 total ----------------
__global__ __launch_bounds__(256) void k_scatter(int layer) {
    int h = threadIdx.x & 63;
    int sub = threadIdx.x >> 6;
    int e0 = blockIdx.x * 32;
    float* dst = layer ? &g_o2[0][0] : &g_o1[0][0];
#pragma unroll
    for (int q = 0; q < 8; q++) {
        int e = e0 + q * 4 + sub;
        int n = e >> 3, k = e & 7;
        int col  = g_idx[n][k];
        float w  = g_vals[n][k];
        float nr = g_dinv[n] * w * g_dinv[col];
        atomicAdd(&dst[col * 64 + h], nr * g_xw[n][h]);
    }
}

// ---------------- self-loop + bias + relu (layer 0) ----------------
__global__ void k_finish(const float* __restrict__ bias) {
    int i = blockIdx.x * blockDim.x + threadIdx.x;
    if (i >= NT * HH) return;
    int t = i >> 6, h = i & 63;
    float* buf = &g_o1[0][0];
    float d = g_dinv[t];
    float v = buf[i] + d * d * (&g_xw[0][0])[i] + bias[h];
    buf[i] = v > 0.f ? v : 0.f;
}

// ---------------- layer-1 finish + BN stats fused ----------------
__global__ __launch_bounds__(256) void k_finish_stats(const float* __restrict__ bias) {
    int h = threadIdx.x & 63, part = threadIdx.x >> 6;
    int rbase = blockIdx.x * 64;
    float* o2 = &g_o2[0][0];
    const float* xw = &g_xw[0][0];
    float bb = bias[h];
    float s = 0.f, s2 = 0.f;
#pragma unroll 4
    for (int sI = 0; sI < 16; sI++) {
        int t = rbase + part + 4 * sI;
        float d = g_dinv[t];
        int i = t * 64 + h;
        float v = o2[i] + d * d * xw[i] + bb;
        v = v > 0.f ? v : 0.f;
        o2[i] = v;
        s += v; s2 += v * v;
    }
    __shared__ float ss[4][64], sq[4][64];
    ss[part][h] = s; sq[part][h] = s2;
    __syncthreads();
    if (threadIdx.x < 64) {
        atomicAdd(&g_sum[h], ss[0][h] + ss[1][h] + ss[2][h] + ss[3][h]);
        atomicAdd(&g_sqs[h], sq[0][h] + sq[1][h] + sq[2][h] + sq[3][h]);
    }
}

// ---------------- fold BN into predictor ----------------
__global__ void k_prep(const float* __restrict__ gamma, const float* __restrict__ beta,
                       const float* __restrict__ Wp, const float* __restrict__ bp) {
    __shared__ float ssc[64], ssh[64];
    int tid = threadIdx.x;
    if (tid < 64) {
        float mu  = g_sum[tid] * (1.f / 8192.f);
        float var = g_sqs[tid] * (1.f / 8192.f) - mu * mu;
        float sc  = gamma[tid] * rsqrtf(var + 1e-5f);
        ssc[tid] = sc;
        ssh[tid] = beta[tid] - mu * sc;
    }
    __syncthreads();
    for (int e = tid; e < OUTD * HH; e += 256) g_Wps[e] = Wp[e] * ssc[e & 63];
    if (tid < OUTD) {
        float a = bp[tid];
        for (int h = 0; h < 64; h++) a += ssh[h] * Wp[tid * 64 + h];
        g_bps[tid] = a;
    }
}

// ---------------- final projection ----------------
__global__ __launch_bounds__(256) void k_out(float* __restrict__ out) {
    int t0 = blockIdx.x * 8;
    __shared__ float sr[8][64];
    int tid = threadIdx.x;
    const float* o2 = &g_o2[0][0];
    for (int e = tid; e < 512; e += 256) sr[e >> 6][e & 63] = o2[(t0 + (e >> 6)) * 64 + (e & 63)];
    __syncthreads();
    int tl = tid >> 5, o = tid & 31;
    float acc = g_bps[o];
#pragma unroll 1
    for (int h = 0; h < 64; h++) acc += sr[tl][h] * g_Wps[o * 64 + h];
    out[(t0 + tl) * 32 + o] = acc;
}

extern "C" void kernel_launch(void* const* d_in, const int* in_sizes, int n_in,
                              void* d_out, int out_size) {
    const float* x_seq = (const float*)d_in[0];
    const float* Wih_s = (const float*)d_in[1];
    const float* Whh_s = (const float*)d_in[2];
    const float* bih_s = (const float*)d_in[3];
    const float* bhh_s = (const float*)d_in[4];
    const float* Wih   = (const float*)d_in[5];
    const float* Whh   = (const float*)d_in[6];
    const float* bih   = (const float*)d_in[7];
    const float* bhh   = (const float*)d_in[8];
    const float* W1    = (const float*)d_in[9];
    const float* b1    = (const float*)d_in[10];
    const float* W2    = (const float*)d_in[11];
    const float* b2    = (const float*)d_in[12];
    const float* gamma = (const float*)d_in[13];
    const float* beta  = (const float*)d_in[14];
    const float* Wp    = (const float*)d_in[15];
    const float* bp    = (const float*)d_in[16];
    float* out = (float*)d_out;

    k_zero<<<512, 256>>>();
    k_xp<<<dim3(256, 2), 192>>>(x_seq, Wih_s, bih_s, Wih, bih);
    k_gru<<<dim3(CCH, 2), 192>>>(Whh_s, bhh_s, Whh, bhh);
    k_sim<<<dim3(32, 4), 512>>>();
    k_topk<<<1024, 256>>>();
    k_dinv<<<32, 256>>>();
    k_xw<<<512, 256>>>(0, W1);
    k_scatter<<<2048, 256>>>(0);
    k_finish<<<2048, 256>>>(b1);
    k_xw<<<512, 256>>>(1, W2);
    k_scatter<<<2048, 256>>>(1);
    k_finish_stats<<<128, 256>>>(b2);
    k_prep<<<1, 256>>>(gamma, beta, Wp, bp);
    k_out<<<1024, 256>>>(out);
}

// round 11
// speedup vs baseline: 1.4207x; 1.0513x over previous
#include <cuda_runtime.h>

#define NB   4
#define NN   2048
#define NT   8192
#define HH   64
#define G3   192
#define KK   8
#define OUTD 32
#define CCH  64
#define CL   128
#define CW   96

typedef unsigned long long ull;

__device__ __forceinline__ ull ffma2(ull a, ull b, ull c) {
    ull d; asm("fma.rn.f32x2 %0, %1, %2, %3;" : "=l"(d) : "l"(a), "l"(b), "l"(c)); return d;
}
__device__ __forceinline__ float2 upk(ull a) {
    float2 r; asm("mov.b64 {%0,%1}, %2;" : "=f"(r.x), "=f"(r.y) : "l"(a)); return r;
}

// ---------------- device scratch (no allocations) ----------------
__device__ float g_xp[2][NT][G3];
__device__ float g_h[2][NT][HH];
__device__ float g_sim[NB * NN * NN];
__device__ float g_vals[NT][KK];
__device__ int   g_idx[NT][KK];
__device__ float g_deg[NT];
__device__ float g_dinv[NT];
__device__ float g_xw[NT][HH];
__device__ float g_o1[NT][HH];
__device__ float g_o2[NT][HH];
__device__ float g_sum[HH];
__device__ float g_sqs[HH];
__device__ float g_Wps[OUTD * HH];
__device__ float g_bps[OUTD];

// ---------------- xp = seq @ Wih.T + bih (both GRUs) ----------------
__global__ __launch_bounds__(192) void k_xp(const float* __restrict__ x_seq,
                                            const float* __restrict__ W0, const float* __restrict__ bi0,
                                            const float* __restrict__ W1, const float* __restrict__ bi1)
{
    int gi = blockIdx.y;
    const float* W  = gi ? W1  : W0;
    const float* bi = gi ? bi1 : bi0;
    int t0 = blockIdx.x * 32;
    int b  = t0 >> 11;
    int n0 = t0 & 2047;
    __shared__ __align__(16) float sT[64 * 32];   // sT[f*32+tt]
    int tid = threadIdx.x;
    for (int e = tid; e < 2048; e += 192) {
        int f = e >> 5, tt = e & 31;
        sT[e] = x_seq[((b * 8 + 7) * 64 + f) * 2048 + n0 + tt];
    }
    float w[64];
    const float4* wr = (const float4*)(W + tid * 64);
#pragma unroll
    for (int q = 0; q < 16; q++) { float4 v = wr[q]; w[4*q]=v.x; w[4*q+1]=v.y; w[4*q+2]=v.z; w[4*q+3]=v.w; }
    float bb = bi[tid];
    __syncthreads();
#pragma unroll 1
    for (int tg = 0; tg < 8; tg++) {
        float a0 = bb, a1 = bb, a2 = bb, a3 = bb;
#pragma unroll
        for (int k = 0; k < 64; k++) {
            float4 sv = *(const float4*)&sT[k * 32 + tg * 4];
            a0 += w[k] * sv.x; a1 += w[k] * sv.y; a2 += w[k] * sv.z; a3 += w[k] * sv.w;
        }
        int tt = tg * 4;
        g_xp[gi][t0 + tt    ][tid] = a0;
        g_xp[gi][t0 + tt + 1][tid] = a1;
        g_xp[gi][t0 + tt + 2][tid] = a2;
        g_xp[gi][t0 + tt + 3][tid] = a3;
    }
}

// ---------------- chunked GRU scan (contraction / warmup trick), 2-deep prefetch ----------------
__global__ __launch_bounds__(192, 1) void k_gru(const float* __restrict__ Whh0, const float* __restrict__ bhh0,
                                                const float* __restrict__ Whh1, const float* __restrict__ bhh1)
{
    int gi = blockIdx.y;
    const float* Whh = gi ? Whh1 : Whh0;
    const float* bhh = gi ? bhh1 : bhh0;
    int c = blockIdx.x;
    int tstart = c * CL - CW; if (tstart < 0) tstart = 0;
    int twrite = c * CL;
    int tend   = c * CL + CL;
    int tid = threadIdx.x;

    ull w2[32];
    const ull* wr = (const ull*)(Whh + tid * HH);
#pragma unroll
    for (int q = 0; q < 32; q++) w2[q] = wr[q];
    float bb = bhh[tid];

    __shared__ __align__(16) float shh[HH];
    __shared__ float shs[G3];
    __shared__ float sxp[G3];
    if (tid < HH) shh[tid] = 0.f;
    __syncthreads();

    const float* xp = &g_xp[gi][0][0];
    float x0 = xp[tstart * G3 + tid];
    int t1 = (tstart + 1 < tend) ? tstart + 1 : tend - 1;
    float x1 = xp[t1 * G3 + tid];

#pragma unroll 1
    for (int t = tstart; t < tend; t++) {
        int tn = (t + 2 < tend) ? (t + 2) : (tend - 1);
        float x2 = xp[tn * G3 + tid];            // 2-deep prefetch covers L2 latency

        const ull* hv = (const ull*)shh;
        ull a0 = 0ull, a1 = 0ull;
#pragma unroll
        for (int q = 0; q < 32; q += 2) {
            a0 = ffma2(w2[q],     hv[q],     a0);
            a1 = ffma2(w2[q + 1], hv[q + 1], a1);
        }
        float2 p0 = upk(a0), p1 = upk(a1);
        float hp = (p0.x + p0.y) + (p1.x + p1.y) + bb;
        shs[tid] = hp;
        sxp[tid] = x0;
        __syncthreads();
        if (tid < HH) {
            float r  = __fdividef(1.f, 1.f + __expf(-(sxp[tid]       + shs[tid])));
            float z  = __fdividef(1.f, 1.f + __expf(-(sxp[tid + 64]  + shs[tid + 64])));
            float a  = sxp[tid + 128] + r * shs[tid + 128];
            float ng = 1.f - __fdividef(2.f, __expf(2.f * a) + 1.f);   // tanh
            float hn = (1.f - z) * ng + z * shh[tid];
            shh[tid] = hn;
            if (t >= twrite) g_h[gi][t][tid] = hn;
        }
        __syncthreads();
        x0 = x1; x1 = x2;
    }
}

// ---------------- similarity: 64-row blocks, 512 threads, f32x2 FMA; inits g_deg ----------------
__global__ __launch_bounds__(512, 1) void k_sim() {
    __shared__ __align__(16) float sA[64 * 66];
    __shared__ __align__(16) float sB[256 * 66];
    int b = blockIdx.y, r0 = blockIdx.x * 64;
    int tid = threadIdx.x, w = tid >> 5, mp = tid & 31;
    int rg = w >> 1, half = w & 1;     // rowgroup 0..7, column half 0..1
    int base = b * NN;

    if (tid < 64) g_deg[base + r0 + tid] = 1.0f;    // self-loop weight (before k_topk atomics)

    for (int e = tid; e < 64 * 32; e += 512) {
        int r = e >> 5, c2 = e & 31;
        *(float2*)&sA[r * 66 + c2 * 2] = *(const float2*)&g_h[0][base + r0 + r][c2 * 2];
    }

    ull acc[8][4];
#pragma unroll
    for (int r = 0; r < 8; r++)
#pragma unroll
        for (int j = 0; j < 4; j++) acc[r][j] = 0ull;

#pragma unroll 1
    for (int tile = 0; tile < 8; tile++) {
        __syncthreads();
        for (int e = tid; e < 256 * 32; e += 512) {
            int r = e >> 5, c2 = e & 31;
            *(float2*)&sB[r * 66 + c2 * 2] = *(const float2*)&g_h[0][base + tile * 256 + r][c2 * 2];
        }
        __syncthreads();
#pragma unroll 4
        for (int kc = 0; kc < 32; kc++) {
            ull bv[4];
#pragma unroll
            for (int j = 0; j < 4; j++) bv[j] = *(const ull*)&sB[(mp + 32 * j + 128 * half) * 66 + 2 * kc];
#pragma unroll
            for (int r = 0; r < 8; r++) {
                ull av = *(const ull*)&sA[(rg * 8 + r) * 66 + 2 * kc];
#pragma unroll
                for (int j = 0; j < 4; j++) acc[r][j] = ffma2(av, bv[j], acc[r][j]);
            }
        }
#pragma unroll
        for (int r = 0; r < 8; r++) {
            int row = r0 + rg * 8 + r;
#pragma unroll
            for (int j = 0; j < 4; j++) {
                int m = tile * 256 + mp + 32 * j + 128 * half;
                float2 p = upk(acc[r][j]);
                float v = p.x + p.y;
                if (m == row) v = -1e9f;
                g_sim[(base + row) * NN + m] = v;
                acc[r][j] = 0ull;
            }
        }
    }
}

// ---------------- top-8 per row (float4 scan + warp shuffle merge) + degree atomics ----------------
__global__ __launch_bounds__(256) void k_topk() {
    int warp = threadIdx.x >> 5, lane = threadIdx.x & 31;
    int t = blockIdx.x * 8 + warp;
    int b = t >> 11;
    const float4* row4 = (const float4*)&g_sim[t * NN];
    float vv[KK]; int ii[KK];
#pragma unroll
    for (int q = 0; q < KK; q++) { vv[q] = -3e38f; ii[q] = 0; }
#pragma unroll 1
    for (int j = 0; j < 16; j++) {
        float4 v4 = row4[j * 32 + lane];
        int m0 = (j * 32 + lane) * 4;
        float vs[4] = {v4.x, v4.y, v4.z, v4.w};
#pragma unroll
        for (int c = 0; c < 4; c++) {
            float v = vs[c];
            if (v > vv[7]) {
                vv[7] = v; ii[7] = m0 + c;
#pragma unroll
                for (int s = 7; s > 0; s--) {
                    if (vv[s] > vv[s - 1]) {
                        float tv = vv[s]; vv[s] = vv[s - 1]; vv[s - 1] = tv;
                        int   ti = ii[s]; ii[s] = ii[s - 1]; ii[s - 1] = ti;
                    }
                }
            }
        }
    }
    int head = 0;
#pragma unroll
    for (int q = 0; q < KK; q++) {
        float myv = (head < KK) ? vv[head] : -3e38f;
        int   myi = (head < KK) ? ii[head] : 0;
        float bestv = myv; int besti = myi; int bestl = lane;
#pragma unroll
        for (int off = 16; off > 0; off >>= 1) {
            float ov = __shfl_xor_sync(0xffffffffu, bestv, off);
            int   oi = __shfl_xor_sync(0xffffffffu, besti, off);
            int   ol = __shfl_xor_sync(0xffffffffu, bestl, off);
            if (ov > bestv || (ov == bestv && ol < bestl)) { bestv = ov; besti = oi; bestl = ol; }
        }
        if (lane == bestl) head++;
        if (lane == 0) {
            g_vals[t][q] = bestv;
            int col = b * NN + besti;
            g_idx[t][q] = col;
            atomicAdd(&g_deg[col], bestv);
        }
    }
}

// ---------------- layer-0 xw = h_out @ W1.T ; also dinv + zero o1 ----------------
__global__ __launch_bounds__(256) void k_xw1(const float* __restrict__ W) {
    int t0 = blockIdx.x * 16;
    __shared__ float sW[64][65];
    __shared__ float sx[16][64];
    int tid = threadIdx.x;
    const float* src = &g_h[1][0][0];
    for (int e = tid; e < 4096; e += 256) sW[e >> 6][e & 63] = W[e];
    for (int e = tid; e < 1024; e += 256) {
        sx[e >> 6][e & 63] = src[(t0 + (e >> 6)) * 64 + (e & 63)];
        g_o1[0][t0 * 64 + e] = 0.f;                      // zero scatter dest
    }
    if (tid < 16) {
        float r = rsqrtf(g_deg[t0 + tid]);
        if (isinf(r)) r = 0.f;
        g_dinv[t0 + tid] = r;
    }
    __syncthreads();
    int h = tid & 63, tq = tid >> 6;
    float acc[4] = {0.f, 0.f, 0.f, 0.f};
#pragma unroll 1
    for (int k = 0; k < 64; k++) {
        float wv = sW[h][k];
#pragma unroll
        for (int r = 0; r < 4; r++) acc[r] += wv * sx[tq * 4 + r][k];
    }
    float* xw = &g_xw[0][0];
#pragma unroll
    for (int r = 0; r < 4; r++) xw[(t0 + tq * 4 + r) * 64 + h] = acc[r];
}

// ---------------- layer-1 xw: fused finish(layer0) + GEMM ; zero o2 + BN accs ----------------
__global__ __launch_bounds__(256) void k_xw2(const float* __restrict__ W, const float* __restrict__ b1) {
    int t0 = blockIdx.x * 16;
    __shared__ float sW[64][65];
    __shared__ float sx[16][64];
    int tid = threadIdx.x;
    for (int e = tid; e < 4096; e += 256) sW[e >> 6][e & 63] = W[e];
    for (int e = tid; e < 1024; e += 256) {
        int t = t0 + (e >> 6), h = e & 63;
        float d = g_dinv[t];
        float v = g_o1[0][t * 64 + h] + d * d * g_xw[0][t * 64 + h] + b1[h];
        sx[e >> 6][h] = v > 0.f ? v : 0.f;               // finished layer-0 output, in smem only
        g_o2[0][t0 * 64 + e] = 0.f;                      // zero scatter dest
    }
    if (t0 == 0 && tid < 64) { g_sum[tid] = 0.f; g_sqs[tid] = 0.f; }
    __syncthreads();
    int h = tid & 63, tq = tid >> 6;
    float acc[4] = {0.f, 0.f, 0.f, 0.f};
#pragma unroll 1
    for (int k = 0; k < 64; k++) {
        float wv = sW[h][k];
#pragma unroll
        for (int r = 0; r < 4; r++) acc[r] += wv * sx[tq * 4 + r][k];
    }
    float* xw = &g_xw[0][0];
#pragma unroll
    for (int r = 0; r < 4; r++) xw[(t0 + tq * 4 + r) * 64 + h] = acc[r];
}

// ---------------- edge scatter (atomics), 32 edges per block, 65536 total ----------------
__global__ __launch_bounds__(256) void k_scatter(int layer) {
    int h = threadIdx.x & 63;
    int sub = threadIdx.x >> 6;
    int e0 = blockIdx.x * 32;
    float* dst = layer ? &g_o2[0][0] : &g_o1[0][0];
#pragma unroll
    for (int q = 0; q < 8; q++) {
        int e = e0 + q * 4 + sub;
        int n = e >> 3, k = e & 7;
        int col  = g_idx[n][k];
        float w  = g_vals[n][k];
        float nr = g_dinv[n] * w * g_dinv[col];
        atomicAdd(&dst[col * 64 + h], nr * g_xw[n][h]);
    }
}

// ---------------- layer-1 finish + BN stats fused ----------------
__global__ __launch_bounds__(256) void k_finish_stats(const float* __restrict__ bias) {
    int h = threadIdx.x & 63, part = threadIdx.x >> 6;
    int rbase = blockIdx.x * 64;
    float* o2 = &g_o2[0][0];
    const float* xw = &g_xw[0][0];
    float bb = bias[h];
    float s = 0.f, s2 = 0.f;
#pragma unroll 4
    for (int sI = 0; sI < 16; sI++) {
        int t = rbase + part + 4 * sI;
        float d = g_dinv[t];
        int i = t * 64 + h;
        float v = o2[i] + d * d * xw[i] + bb;
        v = v > 0.f ? v : 0.f;
        o2[i] = v;
        s += v; s2 += v * v;
    }
    __shared__ float ss[4][64], sq[4][64];
    ss[part][h] = s; sq[part][h] = s2;
    __syncthreads();
    if (threadIdx.x < 64) {
        atomicAdd(&g_sum[h], ss[0][h] + ss[1][h] + ss[2][h] + ss[3][h]);
        atomicAdd(&g_sqs[h], sq[0][h] + sq[1][h] + sq[2][h] + sq[3][h]);
    }
}

// ---------------- fold BN into predictor ----------------
__global__ void k_prep(const float* __restrict__ gamma, const float* __restrict__ beta,
                       const float* __restrict__ Wp, const float* __restrict__ bp) {
    __shared__ float ssc[64], ssh[64];
    int tid = threadIdx.x;
    if (tid < 64) {
        float mu  = g_sum[tid] * (1.f / 8192.f);
        float var = g_sqs[tid] * (1.f / 8192.f) - mu * mu;
        float sc  = gamma[tid] * rsqrtf(var + 1e-5f);
        ssc[tid] = sc;
        ssh[tid] = beta[tid] - mu * sc;
    }
    __syncthreads();
    for (int e = tid; e < OUTD * HH; e += 256) g_Wps[e] = Wp[e] * ssc[e & 63];
    if (tid < OUTD) {
        float a = bp[tid];
        for (int h = 0; h < 64; h++) a += ssh[h] * Wp[tid * 64 + h];
        g_bps[tid] = a;
    }
}

// ---------------- final projection ----------------
__global__ __launch_bounds__(256) void k_out(float* __restrict__ out) {
    int t0 = blockIdx.x * 8;
    __shared__ float sr[8][64];
    int tid = threadIdx.x;
    const float* o2 = &g_o2[0][0];
    for (int e = tid; e < 512; e += 256) sr[e >> 6][e & 63] = o2[(t0 + (e >> 6)) * 64 + (e & 63)];
    __syncthreads();
    int tl = tid >> 5, o = tid & 31;
    float acc = g_bps[o];
#pragma unroll 1
    for (int h = 0; h < 64; h++) acc += sr[tl][h] * g_Wps[o * 64 + h];
    out[(t0 + tl) * 32 + o] = acc;
}

extern "C" void kernel_launch(void* const* d_in, const int* in_sizes, int n_in,
                              void* d_out, int out_size) {
    const float* x_seq = (const float*)d_in[0];
    const float* Wih_s = (const float*)d_in[1];
    const float* Whh_s = (const float*)d_in[2];
    const float* bih_s = (const float*)d_in[3];
    const float* bhh_s = (const float*)d_in[4];
    const float* Wih   = (const float*)d_in[5];
    const float* Whh   = (const float*)d_in[6];
    const float* bih   = (const float*)d_in[7];
    const float* bhh   = (const float*)d_in[8];
    const float* W1    = (const float*)d_in[9];
    const float* b1    = (const float*)d_in[10];
    const float* W2    = (const float*)d_in[11];
    const float* b2    = (const float*)d_in[12];
    const float* gamma = (const float*)d_in[13];
    const float* beta  = (const float*)d_in[14];
    const float* Wp    = (const float*)d_in[15];
    const float* bp    = (const float*)d_in[16];
    float* out = (float*)d_out;

    k_xp<<<dim3(256, 2), 192>>>(x_seq, Wih_s, bih_s, Wih, bih);
    k_gru<<<dim3(CCH, 2), 192>>>(Whh_s, bhh_s, Whh, bhh);
    k_sim<<<dim3(32, 4), 512>>>();
    k_topk<<<1024, 256>>>();
    k_xw1<<<512, 256>>>(W1);
    k_scatter<<<2048, 256>>>(0);
    k_xw2<<<512, 256>>>(W2, b1);
    k_scatter<<<2048, 256>>>(1);
    k_finish_stats<<<128, 256>>>(b2);
    k_prep<<<1, 256>>>(gamma, beta, Wp, bp);
    k_out<<<1024, 256>>>(out);
}